// round 8
// baseline (speedup 1.0000x reference)
#include <cuda_runtime.h>
#include <cuda_bf16.h>
#include <cstdint>

// Problem dims
#define Bb   4
#define Ss   512
#define Dd   1024
#define Hh   16
#define HDh  64
#define KR   64
#define Mrows (Bb*Ss)          // 2048
#define THREE_D (3*Dd)         // 3072

__device__ __constant__ float kSCALE = 0.125f;   // 1/sqrt(64)
#define ALPHA_F 0.25f

// ---------------------------------------------------------------------------
// Scratch (device globals; no allocation allowed)
// ---------------------------------------------------------------------------
__device__ float    g_qkv[3*Bb*Hh*Ss*HDh];      // [t][b*H+h][s][hd] fp32
__device__ float    g_ks [Bb*Hh*Ss*HDh];        // smoothed K
__device__ float    g_vs [Bb*Hh*Ss*HDh];        // smoothed V

// bf16 hi/lo split operands for tensor-core GEMMs
__device__ uint16_t g_xh[Mrows*Dd],     g_xl[Mrows*Dd];       // x split [M][K]
__device__ uint16_t g_wqkvT_h[THREE_D*Dd], g_wqkvT_l[THREE_D*Dd]; // W_qkv^T [N][K]
__device__ uint16_t g_woutT_h[Dd*Dd],   g_woutT_l[Dd*Dd];     // W_out^T [N][K]
__device__ uint16_t g_aoh[Mrows*Dd],    g_aol[Mrows*Dd];      // attn out split [M][K]

// ---------------------------------------------------------------------------
// bf16 split helpers
// ---------------------------------------------------------------------------
__device__ __forceinline__ uint16_t f2bf(float f) {
    __nv_bfloat16 h = __float2bfloat16(f);
    return __bfloat16_as_ushort(h);
}
__device__ __forceinline__ float bf2f(uint16_t u) {
    __nv_bfloat16_raw r; r.x = u;
    return __bfloat162float((__nv_bfloat16)r);
}
__device__ __forceinline__ void split2(float f, uint16_t& h, uint16_t& l) {
    h = f2bf(f);
    l = f2bf(f - bf2f(h));
}

// ---------------------------------------------------------------------------
// mma.sync m16n8k16 bf16 (fp32 accumulate)
// ---------------------------------------------------------------------------
__device__ __forceinline__ void mma_bf16(float* d, const uint32_t* a,
                                         uint32_t b0, uint32_t b1) {
    asm volatile(
        "mma.sync.aligned.m16n8k16.row.col.f32.bf16.bf16.f32 "
        "{%0,%1,%2,%3}, {%4,%5,%6,%7}, {%8,%9}, {%0,%1,%2,%3};\n"
        : "+f"(d[0]), "+f"(d[1]), "+f"(d[2]), "+f"(d[3])
        : "r"(a[0]), "r"(a[1]), "r"(a[2]), "r"(a[3]), "r"(b0), "r"(b1));
}

// ---------------------------------------------------------------------------
// Prep 1: element-wise split of a row-major fp32 matrix into bf16 hi/lo
// one float4 per thread
// ---------------------------------------------------------------------------
__global__ __launch_bounds__(256) void split_rows_kernel(
    const float4* __restrict__ in, uint2* __restrict__ oh,
    uint2* __restrict__ ol, int n4)
{
    int i = blockIdx.x*blockDim.x + threadIdx.x;
    if (i >= n4) return;
    float4 f = in[i];
    uint16_t h0,l0,h1,l1,h2,l2,h3,l3;
    split2(f.x, h0, l0); split2(f.y, h1, l1);
    split2(f.z, h2, l2); split2(f.w, h3, l3);
    oh[i] = make_uint2((uint32_t)h0 | ((uint32_t)h1<<16),
                       (uint32_t)h2 | ((uint32_t)h3<<16));
    ol[i] = make_uint2((uint32_t)l0 | ((uint32_t)l1<<16),
                       (uint32_t)l2 | ((uint32_t)l3<<16));
}

// ---------------------------------------------------------------------------
// Prep 2: transpose fp32 [Kin][Nin] -> bf16 hi/lo [Nin][Kin]  (32x32 tiles)
// ---------------------------------------------------------------------------
__global__ __launch_bounds__(256) void transpose_split_kernel(
    const float* __restrict__ in, int Kin, int Nin,
    uint16_t* __restrict__ oh, uint16_t* __restrict__ ol)
{
    __shared__ float t[32][33];
    const int bx = blockIdx.x*32;   // n
    const int by = blockIdx.y*32;   // k
    const int tx = threadIdx.x;     // 0..31
    const int ty = threadIdx.y;     // 0..7
    #pragma unroll
    for (int i = 0; i < 32; i += 8)
        t[ty+i][tx] = in[(size_t)(by+ty+i)*Nin + bx+tx];
    __syncthreads();
    #pragma unroll
    for (int i = 0; i < 32; i += 8) {
        float f = t[tx][ty+i];
        size_t o = (size_t)(bx+ty+i)*Kin + by+tx;   // out[n][k]
        uint16_t h, l; split2(f, h, l);
        oh[o] = h; ol[o] = l;
    }
}

// ---------------------------------------------------------------------------
// Tensor-core GEMM, bf16x3 split: C[M,N] = A[M,K] @ B[K,N] + bias
//   A given as hi/lo bf16 row-major [M][K]
//   B given as hi/lo bf16 TRANSPOSED [N][K]
// Tile: BM=BN=128, BK=16, 256 thr, 8 warps (4m x 2n), warp tile 32x64.
// SCATTER: epilogue scatters into g_qkv [t][bh][s][hd] layout.
// A_FROM_AO: A comes from g_aoh/g_aol device globals.
// ---------------------------------------------------------------------------
#define SSTR 24   // smem row stride in bf16 elements (48B = 12 banks, 16B-aligned)

template<bool SCATTER, bool A_FROM_AO>
__global__ __launch_bounds__(256) void gemm_bf16x3(
    int M, int N, int Kd,
    const uint16_t* __restrict__ Agh_in, const uint16_t* __restrict__ Agl_in,
    const uint16_t* __restrict__ Bgh, const uint16_t* __restrict__ Bgl,
    const float* __restrict__ bias, float* __restrict__ C)
{
    __shared__ uint16_t sAh[128*SSTR], sAl[128*SSTR];
    __shared__ uint16_t sBh[128*SSTR], sBl[128*SSTR];

    const uint16_t* Agh = A_FROM_AO ? (const uint16_t*)g_aoh : Agh_in;
    const uint16_t* Agl = A_FROM_AO ? (const uint16_t*)g_aol : Agl_in;

    const int tid  = threadIdx.x;
    const int cCol = blockIdx.x;
    const int cRow = blockIdx.y;

    // global loads: each thread owns one uint4 (8 bf16) per matrix per tile
    const int lrow = tid >> 1;         // 0..127
    const int c8   = tid & 1;          // which 8-elem half of the 16-wide slab
    const size_t aBase = (size_t)(cRow*128 + lrow)*Kd + c8*8;
    const size_t bBase = (size_t)(cCol*128 + lrow)*Kd + c8*8;
    const int sidx = lrow*SSTR + c8*8;

    const int wid  = tid >> 5, lane = tid & 31;
    const int wm = (wid & 3)*32;       // warp row base
    const int wn = (wid >> 2)*64;      // warp col base
    const int g  = lane >> 2, q = lane & 3;

    float acc[2][8][4];
    #pragma unroll
    for (int mt = 0; mt < 2; mt++)
        #pragma unroll
        for (int nt = 0; nt < 8; nt++)
            #pragma unroll
            for (int e = 0; e < 4; e++) acc[mt][nt][e] = 0.f;

    uint4 pAh = *(const uint4*)(Agh + aBase);
    uint4 pAl = *(const uint4*)(Agl + aBase);
    uint4 pBh = *(const uint4*)(Bgh + bBase);
    uint4 pBl = *(const uint4*)(Bgl + bBase);

    for (int kt = 16; kt <= Kd; kt += 16) {
        *(uint4*)&sAh[sidx] = pAh;  *(uint4*)&sAl[sidx] = pAl;
        *(uint4*)&sBh[sidx] = pBh;  *(uint4*)&sBl[sidx] = pBl;
        __syncthreads();

        if (kt < Kd) {
            pAh = *(const uint4*)(Agh + aBase + kt);
            pAl = *(const uint4*)(Agl + aBase + kt);
            pBh = *(const uint4*)(Bgh + bBase + kt);
            pBl = *(const uint4*)(Bgl + bBase + kt);
        }

        // load A fragments (2 m-tiles, hi+lo)
        uint32_t ah[2][4], al[2][4];
        #pragma unroll
        for (int mt = 0; mt < 2; mt++) {
            const int r = wm + mt*16 + g;
            ah[mt][0] = *(const uint32_t*)&sAh[ r    *SSTR + 2*q    ];
            ah[mt][1] = *(const uint32_t*)&sAh[(r+8)*SSTR + 2*q    ];
            ah[mt][2] = *(const uint32_t*)&sAh[ r    *SSTR + 2*q + 8];
            ah[mt][3] = *(const uint32_t*)&sAh[(r+8)*SSTR + 2*q + 8];
            al[mt][0] = *(const uint32_t*)&sAl[ r    *SSTR + 2*q    ];
            al[mt][1] = *(const uint32_t*)&sAl[(r+8)*SSTR + 2*q    ];
            al[mt][2] = *(const uint32_t*)&sAl[ r    *SSTR + 2*q + 8];
            al[mt][3] = *(const uint32_t*)&sAl[(r+8)*SSTR + 2*q + 8];
        }

        #pragma unroll
        for (int nt = 0; nt < 8; nt++) {
            const int n = wn + nt*8 + g;
            const uint32_t bh0 = *(const uint32_t*)&sBh[n*SSTR + 2*q    ];
            const uint32_t bh1 = *(const uint32_t*)&sBh[n*SSTR + 2*q + 8];
            const uint32_t bl0 = *(const uint32_t*)&sBl[n*SSTR + 2*q    ];
            const uint32_t bl1 = *(const uint32_t*)&sBl[n*SSTR + 2*q + 8];
            #pragma unroll
            for (int mt = 0; mt < 2; mt++) {
                mma_bf16(acc[mt][nt], ah[mt], bh0, bh1);   // hi*hi
                mma_bf16(acc[mt][nt], ah[mt], bl0, bl1);   // hi*lo
                mma_bf16(acc[mt][nt], al[mt], bh0, bh1);   // lo*hi
            }
        }
        __syncthreads();
    }

    // epilogue
    #pragma unroll
    for (int mt = 0; mt < 2; mt++) {
        const int R0 = cRow*128 + wm + mt*16 + g;
        #pragma unroll
        for (int nt = 0; nt < 8; nt++) {
            const int Cc = cCol*128 + wn + nt*8 + 2*q;
            if (SCATTER) {
                #pragma unroll
                for (int e = 0; e < 4; e++) {
                    const int m = (e < 2) ? R0 : R0 + 8;
                    const int n = Cc + (e & 1);
                    const float val = acc[mt][nt][e] + bias[n];
                    const int t  = n >> 10;
                    const int h  = (n >> 6) & 15;
                    const int hd = n & 63;
                    const int b  = m >> 9;
                    const int s  = m & 511;
                    const int bh = b*Hh + h;
                    g_qkv[(((size_t)t*Bb*Hh + bh)*Ss + s)*HDh + hd] = val;
                }
            } else {
                const float b0 = bias[Cc], b1 = bias[Cc+1];
                *(float2*)&C[(size_t)R0*N + Cc] =
                    make_float2(acc[mt][nt][0] + b0, acc[mt][nt][1] + b1);
                *(float2*)&C[(size_t)(R0+8)*N + Cc] =
                    make_float2(acc[mt][nt][2] + b0, acc[mt][nt][3] + b1);
            }
        }
    }
}

// ---------------------------------------------------------------------------
// Neighbor smoothing (unchanged)
// ---------------------------------------------------------------------------
__global__ __launch_bounds__(256) void smooth_kernel()
{
    const int idx = blockIdx.x*blockDim.x + threadIdx.x;
    const int total = Bb*Hh*Ss*16;
    if (idx >= total) return;
    const int f  = idx & 15;
    const int s  = (idx >> 4) & (Ss-1);
    const int bh = idx >> 13;

    const float4* qkv4 = (const float4*)g_qkv;
    const float w0 = 1.0f - ALPHA_F;
    const float w1 = ALPHA_F * 0.5f;
    const int dl = (s > 0)    ? -16 : 0;
    const int dr = (s < Ss-1) ?  16 : 0;

    {
        const int base = (((Bb*Hh) + bh)*Ss + s)*16 + f;
        float4 c = qkv4[base], l = qkv4[base+dl], r = qkv4[base+dr];
        float4 o;
        o.x = w0*c.x + w1*(l.x + r.x);
        o.y = w0*c.y + w1*(l.y + r.y);
        o.z = w0*c.z + w1*(l.z + r.z);
        o.w = w0*c.w + w1*(l.w + r.w);
        ((float4*)g_ks)[(bh*Ss + s)*16 + f] = o;
    }
    {
        const int base = (((2*Bb*Hh) + bh)*Ss + s)*16 + f;
        float4 c = qkv4[base], l = qkv4[base+dl], r = qkv4[base+dr];
        float4 o;
        o.x = w0*c.x + w1*(l.x + r.x);
        o.y = w0*c.y + w1*(l.y + r.y);
        o.z = w0*c.z + w1*(l.z + r.z);
        o.w = w0*c.w + w1*(l.w + r.w);
        ((float4*)g_vs)[(bh*Ss + s)*16 + f] = o;
    }
}

// ---------------------------------------------------------------------------
// Routed attention (epilogue now emits bf16 hi/lo for the out-proj GEMM)
// ---------------------------------------------------------------------------
__global__ __launch_bounds__(256) void attn_kernel(const int* __restrict__ routes)
{
    __shared__ float qs    [8][64];
    __shared__ float attn_s[8][64];
    __shared__ int   rt_s  [8][64];

    const int warp = threadIdx.x >> 5;
    const int lane = threadIdx.x & 31;
    const int gq = blockIdx.x*8 + warp;
    const int s  = gq & (Ss-1);
    const int bh = gq >> 9;

    const float* qrow = g_qkv + ((size_t)bh*Ss + s)*HDh;
    const float* kb   = g_ks + (size_t)bh*Ss*HDh;
    const float* vb   = g_vs + (size_t)bh*Ss*HDh;

    if (lane < 16)
        ((float4*)qs[warp])[lane] = ((const float4*)qrow)[lane];
    const int r0 = routes[s*KR + lane];
    const int r1 = routes[s*KR + 32 + lane];
    rt_s[warp][lane]      = r0;
    rt_s[warp][lane + 32] = r1;
    __syncwarp();

    const float4* k0 = (const float4*)(kb + r0*HDh);
    const float4* k1 = (const float4*)(kb + r1*HDh);
    const float4* q4 = (const float4*)qs[warp];
    float a0 = 0.f, a1 = 0.f;
    #pragma unroll
    for (int d = 0; d < 16; ++d) {
        float4 qv = q4[d];
        float4 x0 = k0[d];
        float4 x1 = k1[d];
        a0 += qv.x*x0.x + qv.y*x0.y + qv.z*x0.z + qv.w*x0.w;
        a1 += qv.x*x1.x + qv.y*x1.y + qv.z*x1.z + qv.w*x1.w;
    }
    float sc0 = (r0 > s) ? -1e9f : a0 * kSCALE;
    float sc1 = (r1 > s) ? -1e9f : a1 * kSCALE;

    float mx = fmaxf(sc0, sc1);
    #pragma unroll
    for (int o = 16; o > 0; o >>= 1)
        mx = fmaxf(mx, __shfl_xor_sync(0xffffffffu, mx, o));
    float e0 = __expf(sc0 - mx);
    float e1 = __expf(sc1 - mx);
    float sum = e0 + e1;
    #pragma unroll
    for (int o = 16; o > 0; o >>= 1)
        sum += __shfl_xor_sync(0xffffffffu, sum, o);
    const float inv = 1.0f / sum;
    attn_s[warp][lane]      = e0 * inv;
    attn_s[warp][lane + 32] = e1 * inv;
    __syncwarp();

    float o0 = 0.f, o1 = 0.f;
    #pragma unroll 8
    for (int j = 0; j < KR; ++j) {
        const int   rj = rt_s[warp][j];
        const float w  = attn_s[warp][j];
        const float2 vv = *(const float2*)(vb + rj*HDh + 2*lane);
        o0 += w*vv.x;
        o1 += w*vv.y;
    }

    // write bf16 hi/lo split directly (feeds out-proj tensor GEMM)
    const int b = bh >> 4;
    const int h = bh & 15;
    uint16_t h0,l0,h1,l1;
    split2(o0, h0, l0);
    split2(o1, h1, l1);
    const size_t u32idx = (((size_t)(b*Ss + s))*Dd + h*HDh)/2 + lane;
    ((uint32_t*)g_aoh)[u32idx] = (uint32_t)h0 | ((uint32_t)h1 << 16);
    ((uint32_t*)g_aol)[u32idx] = (uint32_t)l0 | ((uint32_t)l1 << 16);
}

// ---------------------------------------------------------------------------
extern "C" void kernel_launch(void* const* d_in, const int* in_sizes, int n_in,
                              void* d_out, int out_size)
{
    const float* x      = (const float*)d_in[0];   // [B,S,D]
    const float* w_qkv  = (const float*)d_in[1];   // [D, 3D]
    const float* b_qkv  = (const float*)d_in[2];   // [3D]
    const float* w_out  = (const float*)d_in[3];   // [D, D]
    const float* b_out  = (const float*)d_in[4];   // [D]
    const int*   routes = (const int*)d_in[5];     // [S, K]
    float* out = (float*)d_out;                    // [B,S,D]

    // Prep: split x; transpose+split weights
    {
        const int n4 = Mrows*Dd/4;
        split_rows_kernel<<<(n4 + 255)/256, 256>>>(
            (const float4*)x, (uint2*)g_xh, (uint2*)g_xl, n4);
        dim3 blk(32, 8);
        transpose_split_kernel<<<dim3(THREE_D/32, Dd/32), blk>>>(
            w_qkv, Dd, THREE_D, g_wqkvT_h, g_wqkvT_l);
        transpose_split_kernel<<<dim3(Dd/32, Dd/32), blk>>>(
            w_out, Dd, Dd, g_woutT_h, g_woutT_l);
    }
    // 1) QKV projection (tensor cores) + scatter into [t][bh][s][hd]
    {
        dim3 grid(THREE_D/128, Mrows/128);   // (24, 16)
        gemm_bf16x3<true, false><<<grid, 256>>>(
            Mrows, THREE_D, Dd, g_xh, g_xl, g_wqkvT_h, g_wqkvT_l, b_qkv, nullptr);
    }
    // 2) neighbor smoothing of K/V
    {
        const int total = Bb*Hh*Ss*16;
        smooth_kernel<<<(total + 255)/256, 256>>>();
    }
    // 3) routed attention -> g_aoh/g_aol (bf16 split)
    {
        attn_kernel<<<(Bb*Hh*Ss)/8, 256>>>(routes);
    }
    // 4) output projection (tensor cores)
    {
        dim3 grid(Dd/128, Mrows/128);        // (8, 16)
        gemm_bf16x3<false, true><<<grid, 256>>>(
            Mrows, Dd, Dd, nullptr, nullptr, g_woutT_h, g_woutT_l, b_out, out);
    }
}

// round 11
// speedup vs baseline: 6.6080x; 6.6080x over previous
#include <cuda_runtime.h>
#include <cstdint>

// Problem dims
#define Bb   4
#define Ss   512
#define Dd   1024
#define Hh   16
#define HDh  64
#define KR   64
#define Mrows (Bb*Ss)          // 2048
#define THREE_D (3*Dd)         // 3072

__device__ __constant__ float kSCALE = 0.125f;   // 1/sqrt(64)
#define ALPHA_F 0.25f

// Scratch (device globals; no allocation allowed)
__device__ float g_qkv[3*Bb*Hh*Ss*HDh];   // [t][b*H+h][s][hd]
__device__ float g_ks [Bb*Hh*Ss*HDh];     // smoothed K
__device__ float g_vs [Bb*Hh*Ss*HDh];     // smoothed V
__device__ float g_attnout[Bb*Ss*Dd];     // [B*S, D]

// packed fp32x2 FMA (Blackwell FFMA2; PTX-only encoding)
#define FMA2(d, a, b) \
    asm("fma.rn.f32x2 %0, %1, %2, %0;" : "+l"(d) : "l"(a), "l"(b))

__device__ __forceinline__ unsigned long long dup_f32(float v) {
    unsigned long long r;
    asm("mov.b64 %0, {%1, %1};" : "=l"(r) : "f"(v));
    return r;
}

// ---------------------------------------------------------------------------
// Tiled fp32 GEMM on packed f32x2: C[M,N] = A[M,K] @ B[K,N] + bias[N]
// BM=BN=128, BK=16, TM=8, TN=8 (as 4 packed pairs), 256 threads.
// A staged DUPLICATED in smem (As2[k][2m]=As2[k][2m+1]) so the mainloop loads
// (m,m) pairs directly; B pairs (n0,n1) are natural layout.
// QKV_SCATTER: epilogue scatters into g_qkv [t][bh][s][hd].
// A_FROM_ATTN: A comes from g_attnout.
// ---------------------------------------------------------------------------
template<bool QKV_SCATTER, bool A_FROM_ATTN>
__global__ __launch_bounds__(256, 1) void sgemm2_k(
    int M, int N, int Kd,
    const float* __restrict__ Ain, const float* __restrict__ Bm,
    const float* __restrict__ bias, float* __restrict__ C)
{
    __shared__ float As2[16][256];   // duplicated A: [k][2m],[2m+1]
    __shared__ float Bs [16][128];

    const int tid = threadIdx.x;
    const int cCol = blockIdx.x;   // N tile
    const int cRow = blockIdx.y;   // M tile

    const float* A = (A_FROM_ATTN ? (const float*)g_attnout : Ain) + (size_t)cRow*128*Kd;
    const float* Bp = Bm + cCol*128;

    const int innerRowA = tid >> 2;        // 0..63
    const int innerColA = tid & 3;         // 4-float k-chunk
    const int innerRowB = tid >> 5;        // 0..7
    const int innerColB = tid & 31;        // float4 col

    const int threadCol = tid & 15;        // 0..15
    const int threadRow = tid >> 4;        // 0..15

    unsigned long long acc[8][4];
    #pragma unroll
    for (int i = 0; i < 8; i++)
        #pragma unroll
        for (int j = 0; j < 4; j++) acc[i][j] = 0ull;   // (0.0f, 0.0f)

    // prefetch first tile into registers
    float4 pA0 = *(const float4*)(&A[(size_t)(innerRowA     )*Kd + innerColA*4]);
    float4 pA1 = *(const float4*)(&A[(size_t)(innerRowA + 64)*Kd + innerColA*4]);
    float4 pB0 = *(const float4*)(&Bp[(size_t)(innerRowB    )*N + innerColB*4]);
    float4 pB1 = *(const float4*)(&Bp[(size_t)(innerRowB + 8)*N + innerColB*4]);

    for (int kt = 16; kt <= Kd; kt += 16) {
        // stage A duplicated (STS.64 of (v,v)) and B
        {
            const int m0 = innerRowA, m1 = innerRowA + 64;
            const int kk = innerColA*4;
            *(unsigned long long*)&As2[kk+0][2*m0] = dup_f32(pA0.x);
            *(unsigned long long*)&As2[kk+1][2*m0] = dup_f32(pA0.y);
            *(unsigned long long*)&As2[kk+2][2*m0] = dup_f32(pA0.z);
            *(unsigned long long*)&As2[kk+3][2*m0] = dup_f32(pA0.w);
            *(unsigned long long*)&As2[kk+0][2*m1] = dup_f32(pA1.x);
            *(unsigned long long*)&As2[kk+1][2*m1] = dup_f32(pA1.y);
            *(unsigned long long*)&As2[kk+2][2*m1] = dup_f32(pA1.z);
            *(unsigned long long*)&As2[kk+3][2*m1] = dup_f32(pA1.w);
            *(float4*)(&Bs[innerRowB    ][innerColB*4]) = pB0;
            *(float4*)(&Bs[innerRowB + 8][innerColB*4]) = pB1;
        }
        __syncthreads();

        if (kt < Kd) {   // prefetch next tile
            pA0 = *(const float4*)(&A[(size_t)(innerRowA     )*Kd + kt + innerColA*4]);
            pA1 = *(const float4*)(&A[(size_t)(innerRowA + 64)*Kd + kt + innerColA*4]);
            pB0 = *(const float4*)(&Bp[(size_t)(kt+innerRowB    )*N + innerColB*4]);
            pB1 = *(const float4*)(&Bp[(size_t)(kt+innerRowB + 8)*N + innerColB*4]);
        }

        #pragma unroll
        for (int dot = 0; dot < 16; ++dot) {
            // A pairs: (m,m) duplicated, 8 values = 4x LDS.128
            ulonglong2 a0 = *(const ulonglong2*)&As2[dot][threadRow*16 +  0];
            ulonglong2 a1 = *(const ulonglong2*)&As2[dot][threadRow*16 +  4];
            ulonglong2 a2 = *(const ulonglong2*)&As2[dot][threadRow*16 +  8];
            ulonglong2 a3 = *(const ulonglong2*)&As2[dot][threadRow*16 + 12];
            // B pairs: (n0,n1) natural, 8 values = 2x LDS.128
            ulonglong2 b0 = *(const ulonglong2*)&Bs[dot][threadCol*8];
            ulonglong2 b1 = *(const ulonglong2*)&Bs[dot][threadCol*8 + 4];
            unsigned long long rm[8] = {a0.x, a0.y, a1.x, a1.y,
                                        a2.x, a2.y, a3.x, a3.y};
            unsigned long long rn[4] = {b0.x, b0.y, b1.x, b1.y};
            #pragma unroll
            for (int i = 0; i < 8; i++) {
                FMA2(acc[i][0], rm[i], rn[0]);
                FMA2(acc[i][1], rm[i], rn[1]);
                FMA2(acc[i][2], rm[i], rn[2]);
                FMA2(acc[i][3], rm[i], rn[3]);
            }
        }
        __syncthreads();
    }

    // epilogue: acc[i][j] packs columns (threadCol*8+2j, +2j+1) for row threadRow*8+i
    #pragma unroll
    for (int i = 0; i < 8; i++) {
        const int m = cRow*128 + threadRow*8 + i;
        #pragma unroll
        for (int j = 0; j < 4; j++) {
            const float2 v = *(const float2*)&acc[i][j];
            const int n0 = cCol*128 + threadCol*8 + 2*j;
            if (QKV_SCATTER) {
                const int b  = m >> 9;
                const int s  = m & 511;
                #pragma unroll
                for (int e = 0; e < 2; e++) {
                    const int n  = n0 + e;
                    const float val = (e ? v.y : v.x) + bias[n];
                    const int t  = n >> 10;
                    const int h  = (n >> 6) & 15;
                    const int hd = n & 63;
                    const int bh = b*Hh + h;
                    g_qkv[(((size_t)t*Bb*Hh + bh)*Ss + s)*HDh + hd] = val;
                }
            } else {
                *(float2*)&C[(size_t)m*N + n0] =
                    make_float2(v.x + bias[n0], v.y + bias[n0+1]);
            }
        }
    }
}

// ---------------------------------------------------------------------------
// Neighbor smoothing: k_s[j] = (1-a)k[j] + a/2 (k[clip(j-1)] + k[clip(j+1)])
// ---------------------------------------------------------------------------
__global__ __launch_bounds__(256) void smooth_kernel()
{
    const int idx = blockIdx.x*blockDim.x + threadIdx.x;
    const int total = Bb*Hh*Ss*16;
    if (idx >= total) return;
    const int f  = idx & 15;
    const int s  = (idx >> 4) & (Ss-1);
    const int bh = idx >> 13;

    const float4* qkv4 = (const float4*)g_qkv;
    const float w0 = 1.0f - ALPHA_F;
    const float w1 = ALPHA_F * 0.5f;
    const int dl = (s > 0)    ? -16 : 0;
    const int dr = (s < Ss-1) ?  16 : 0;

    {
        const int base = (((Bb*Hh) + bh)*Ss + s)*16 + f;
        float4 c = qkv4[base], l = qkv4[base+dl], r = qkv4[base+dr];
        float4 o;
        o.x = w0*c.x + w1*(l.x + r.x);
        o.y = w0*c.y + w1*(l.y + r.y);
        o.z = w0*c.z + w1*(l.z + r.z);
        o.w = w0*c.w + w1*(l.w + r.w);
        ((float4*)g_ks)[(bh*Ss + s)*16 + f] = o;
    }
    {
        const int base = (((2*Bb*Hh) + bh)*Ss + s)*16 + f;
        float4 c = qkv4[base], l = qkv4[base+dl], r = qkv4[base+dr];
        float4 o;
        o.x = w0*c.x + w1*(l.x + r.x);
        o.y = w0*c.y + w1*(l.y + r.y);
        o.z = w0*c.z + w1*(l.z + r.z);
        o.w = w0*c.w + w1*(l.w + r.w);
        ((float4*)g_vs)[(bh*Ss + s)*16 + f] = o;
    }
}

// ---------------------------------------------------------------------------
// Routed attention: one warp per query (b,h,s).  (R5 structure, fp32 output)
// ---------------------------------------------------------------------------
__global__ __launch_bounds__(256) void attn_kernel(const int* __restrict__ routes)
{
    __shared__ float qs    [8][64];
    __shared__ float attn_s[8][64];
    __shared__ int   rt_s  [8][64];

    const int warp = threadIdx.x >> 5;
    const int lane = threadIdx.x & 31;
    const int gq = blockIdx.x*8 + warp;      // (b*H + h)*S + s
    const int s  = gq & (Ss-1);
    const int bh = gq >> 9;

    const float* qrow = g_qkv + ((size_t)bh*Ss + s)*HDh;   // t=0
    const float* kb   = g_ks + (size_t)bh*Ss*HDh;
    const float* vb   = g_vs + (size_t)bh*Ss*HDh;

    if (lane < 16)
        ((float4*)qs[warp])[lane] = ((const float4*)qrow)[lane];
    const int r0 = routes[s*KR + lane];
    const int r1 = routes[s*KR + 32 + lane];
    rt_s[warp][lane]      = r0;
    rt_s[warp][lane + 32] = r1;
    __syncwarp();

    const float4* k0 = (const float4*)(kb + r0*HDh);
    const float4* k1 = (const float4*)(kb + r1*HDh);
    const float4* q4 = (const float4*)qs[warp];
    float a0 = 0.f, a1 = 0.f;
    #pragma unroll
    for (int d = 0; d < 16; ++d) {
        float4 qv = q4[d];
        float4 x0 = k0[d];
        float4 x1 = k1[d];
        a0 += qv.x*x0.x + qv.y*x0.y + qv.z*x0.z + qv.w*x0.w;
        a1 += qv.x*x1.x + qv.y*x1.y + qv.z*x1.z + qv.w*x1.w;
    }
    float sc0 = (r0 > s) ? -1e9f : a0 * kSCALE;
    float sc1 = (r1 > s) ? -1e9f : a1 * kSCALE;

    float mx = fmaxf(sc0, sc1);
    #pragma unroll
    for (int o = 16; o > 0; o >>= 1)
        mx = fmaxf(mx, __shfl_xor_sync(0xffffffffu, mx, o));
    float e0 = __expf(sc0 - mx);
    float e1 = __expf(sc1 - mx);
    float sum = e0 + e1;
    #pragma unroll
    for (int o = 16; o > 0; o >>= 1)
        sum += __shfl_xor_sync(0xffffffffu, sum, o);
    const float inv = 1.0f / sum;
    attn_s[warp][lane]      = e0 * inv;
    attn_s[warp][lane + 32] = e1 * inv;
    __syncwarp();

    float o0 = 0.f, o1 = 0.f;
    #pragma unroll 8
    for (int j = 0; j < KR; ++j) {
        const int   rj = rt_s[warp][j];
        const float w  = attn_s[warp][j];
        const float2 vv = *(const float2*)(vb + rj*HDh + 2*lane);
        o0 += w*vv.x;
        o1 += w*vv.y;
    }

    const int b = bh >> 4;
    const int h = bh & 15;
    float2* op = (float2*)(g_attnout + ((size_t)(b*Ss + s))*Dd + h*HDh) + lane;
    *op = make_float2(o0, o1);
}

// ---------------------------------------------------------------------------
extern "C" void kernel_launch(void* const* d_in, const int* in_sizes, int n_in,
                              void* d_out, int out_size)
{
    const float* x      = (const float*)d_in[0];   // [B,S,D]
    const float* w_qkv  = (const float*)d_in[1];   // [D, 3D]
    const float* b_qkv  = (const float*)d_in[2];   // [3D]
    const float* w_out  = (const float*)d_in[3];   // [D, D]
    const float* b_out  = (const float*)d_in[4];   // [D]
    const int*   routes = (const int*)d_in[5];     // [S, K]
    float* out = (float*)d_out;                    // [B,S,D]

    // 1) QKV projection + scatter into [t][bh][s][hd]
    {
        dim3 grid(THREE_D/128, Mrows/128);         // (24, 16)
        sgemm2_k<true, false><<<grid, 256>>>(Mrows, THREE_D, Dd, x, w_qkv, b_qkv, nullptr);
    }
    // 2) neighbor smoothing of K/V
    {
        const int total = Bb*Hh*Ss*16;
        smooth_kernel<<<(total + 255)/256, 256>>>();
    }
    // 3) routed attention -> g_attnout [B*S, D]
    {
        attn_kernel<<<(Bb*Hh*Ss)/8, 256>>>(routes);
    }
    // 4) output projection
    {
        dim3 grid(Dd/128, Mrows/128);              // (8, 16)
        sgemm2_k<false, true><<<grid, 256>>>(Mrows, Dd, Dd, nullptr, w_out, b_out, out);
    }
}

// round 12
// speedup vs baseline: 7.5796x; 1.1470x over previous
#include <cuda_runtime.h>
#include <cstdint>

// Problem dims
#define Bb   4
#define Ss   512
#define Dd   1024
#define Hh   16
#define HDh  64
#define KR   64
#define Mrows (Bb*Ss)          // 2048
#define THREE_D (3*Dd)         // 3072

__device__ __constant__ float kSCALE = 0.125f;   // 1/sqrt(64)
#define ALPHA_F 0.25f

// Scratch (device globals; no allocation allowed)
__device__ float g_qkv[3*Bb*Hh*Ss*HDh];   // [t][b*H+h][s][hd]
__device__ float g_ks [Bb*Hh*Ss*HDh];     // smoothed K
__device__ float g_vs [Bb*Hh*Ss*HDh];     // smoothed V
__device__ float g_attnout[Bb*Ss*Dd];     // [B*S, D]

// packed fp32x2 FMA (Blackwell FFMA2; PTX-only encoding)
#define FMA2(d, a, b) \
    asm("fma.rn.f32x2 %0, %1, %2, %0;" : "+l"(d) : "l"(a), "l"(b))

__device__ __forceinline__ unsigned long long dup_f32(float v) {
    unsigned long long r;
    asm("mov.b64 %0, {%1, %1};" : "=l"(r) : "f"(v));
    return r;
}

// ---------------------------------------------------------------------------
// Tiled fp32 GEMM on packed f32x2: C[M,N] = A[M,K] @ B[K,N] + bias[N]
// BM=BN=128, BK=16, TM=8, TN=8 (4 packed N-pairs), 256 threads.
// A staged NATURAL-transposed As[k][m] (8KB). Per dot: 2 LDS.128 for A
// (lane-group broadcast), duplicate to (a,a) pairs in REGISTERS via mov.b64
// (ALU pipe, parallel to LSU+FMA); B read as natural (n0,n1) pairs
// (2 LDS.128). Per-dot crossbar: 64B/thread = 128 cyc/CTA, co-bound with
// the 128-cyc FFMA2 stream (was 192-cyc LDS-bound with smem-duplicated A).
// QKV_SCATTER: epilogue scatters into g_qkv [t][bh][s][hd].
// A_FROM_ATTN: A comes from g_attnout.
// ---------------------------------------------------------------------------
template<bool QKV_SCATTER, bool A_FROM_ATTN>
__global__ __launch_bounds__(256, 1) void sgemm2_k(
    int M, int N, int Kd,
    const float* __restrict__ Ain, const float* __restrict__ Bm,
    const float* __restrict__ bias, float* __restrict__ C)
{
    __shared__ float As[16][128];   // [k][m] transposed
    __shared__ float Bs[16][128];   // [k][n]

    const int tid = threadIdx.x;
    const int cCol = blockIdx.x;   // N tile
    const int cRow = blockIdx.y;   // M tile

    const float* A = (A_FROM_ATTN ? (const float*)g_attnout : Ain) + (size_t)cRow*128*Kd;
    const float* Bp = Bm + cCol*128;

    const int innerRowA = tid >> 2;        // 0..63
    const int innerColA = tid & 3;         // 4-float k-chunk
    const int innerRowB = tid >> 5;        // 0..7
    const int innerColB = tid & 31;        // float4 col

    const int threadCol = tid & 15;        // 0..15
    const int threadRow = tid >> 4;        // 0..15

    unsigned long long acc[8][4];
    #pragma unroll
    for (int i = 0; i < 8; i++)
        #pragma unroll
        for (int j = 0; j < 4; j++) acc[i][j] = 0ull;   // (0.0f, 0.0f)

    // prefetch first tile into registers
    float4 pA0 = *(const float4*)(&A[(size_t)(innerRowA     )*Kd + innerColA*4]);
    float4 pA1 = *(const float4*)(&A[(size_t)(innerRowA + 64)*Kd + innerColA*4]);
    float4 pB0 = *(const float4*)(&Bp[(size_t)(innerRowB    )*N + innerColB*4]);
    float4 pB1 = *(const float4*)(&Bp[(size_t)(innerRowB + 8)*N + innerColB*4]);

    for (int kt = 16; kt <= Kd; kt += 16) {
        // stage A transposed (scalar STS) and B (STS.128)
        {
            const int m0 = innerRowA, m1 = innerRowA + 64;
            const int kk = innerColA*4;
            As[kk+0][m0] = pA0.x;
            As[kk+1][m0] = pA0.y;
            As[kk+2][m0] = pA0.z;
            As[kk+3][m0] = pA0.w;
            As[kk+0][m1] = pA1.x;
            As[kk+1][m1] = pA1.y;
            As[kk+2][m1] = pA1.z;
            As[kk+3][m1] = pA1.w;
            *(float4*)(&Bs[innerRowB    ][innerColB*4]) = pB0;
            *(float4*)(&Bs[innerRowB + 8][innerColB*4]) = pB1;
        }
        __syncthreads();

        if (kt < Kd) {   // prefetch next tile
            pA0 = *(const float4*)(&A[(size_t)(innerRowA     )*Kd + kt + innerColA*4]);
            pA1 = *(const float4*)(&A[(size_t)(innerRowA + 64)*Kd + kt + innerColA*4]);
            pB0 = *(const float4*)(&Bp[(size_t)(kt+innerRowB    )*N + innerColB*4]);
            pB1 = *(const float4*)(&Bp[(size_t)(kt+innerRowB + 8)*N + innerColB*4]);
        }

        #pragma unroll
        for (int dot = 0; dot < 16; ++dot) {
            // A: 8 floats, 2 LDS.128 (16-lane broadcast), dup to pairs in regs
            float4 a0 = *(const float4*)&As[dot][threadRow*8];
            float4 a1 = *(const float4*)&As[dot][threadRow*8 + 4];
            unsigned long long rm[8];
            rm[0] = dup_f32(a0.x); rm[1] = dup_f32(a0.y);
            rm[2] = dup_f32(a0.z); rm[3] = dup_f32(a0.w);
            rm[4] = dup_f32(a1.x); rm[5] = dup_f32(a1.y);
            rm[6] = dup_f32(a1.z); rm[7] = dup_f32(a1.w);
            // B: natural (n0,n1) pairs, 2 LDS.128
            ulonglong2 b0 = *(const ulonglong2*)&Bs[dot][threadCol*8];
            ulonglong2 b1 = *(const ulonglong2*)&Bs[dot][threadCol*8 + 4];
            unsigned long long rn[4] = {b0.x, b0.y, b1.x, b1.y};
            #pragma unroll
            for (int i = 0; i < 8; i++) {
                FMA2(acc[i][0], rm[i], rn[0]);
                FMA2(acc[i][1], rm[i], rn[1]);
                FMA2(acc[i][2], rm[i], rn[2]);
                FMA2(acc[i][3], rm[i], rn[3]);
            }
        }
        __syncthreads();
    }

    // epilogue: acc[i][j] packs columns (threadCol*8+2j, +2j+1) for row threadRow*8+i
    #pragma unroll
    for (int i = 0; i < 8; i++) {
        const int m = cRow*128 + threadRow*8 + i;
        #pragma unroll
        for (int j = 0; j < 4; j++) {
            const float2 v = *(const float2*)&acc[i][j];
            const int n0 = cCol*128 + threadCol*8 + 2*j;
            if (QKV_SCATTER) {
                const int b  = m >> 9;
                const int s  = m & 511;
                #pragma unroll
                for (int e = 0; e < 2; e++) {
                    const int n  = n0 + e;
                    const float val = (e ? v.y : v.x) + bias[n];
                    const int t  = n >> 10;
                    const int h  = (n >> 6) & 15;
                    const int hd = n & 63;
                    const int bh = b*Hh + h;
                    g_qkv[(((size_t)t*Bb*Hh + bh)*Ss + s)*HDh + hd] = val;
                }
            } else {
                *(float2*)&C[(size_t)m*N + n0] =
                    make_float2(v.x + bias[n0], v.y + bias[n0+1]);
            }
        }
    }
}

// ---------------------------------------------------------------------------
// Neighbor smoothing: k_s[j] = (1-a)k[j] + a/2 (k[clip(j-1)] + k[clip(j+1)])
// ---------------------------------------------------------------------------
__global__ __launch_bounds__(256) void smooth_kernel()
{
    const int idx = blockIdx.x*blockDim.x + threadIdx.x;
    const int total = Bb*Hh*Ss*16;
    if (idx >= total) return;
    const int f  = idx & 15;
    const int s  = (idx >> 4) & (Ss-1);
    const int bh = idx >> 13;

    const float4* qkv4 = (const float4*)g_qkv;
    const float w0 = 1.0f - ALPHA_F;
    const float w1 = ALPHA_F * 0.5f;
    const int dl = (s > 0)    ? -16 : 0;
    const int dr = (s < Ss-1) ?  16 : 0;

    {
        const int base = (((Bb*Hh) + bh)*Ss + s)*16 + f;
        float4 c = qkv4[base], l = qkv4[base+dl], r = qkv4[base+dr];
        float4 o;
        o.x = w0*c.x + w1*(l.x + r.x);
        o.y = w0*c.y + w1*(l.y + r.y);
        o.z = w0*c.z + w1*(l.z + r.z);
        o.w = w0*c.w + w1*(l.w + r.w);
        ((float4*)g_ks)[(bh*Ss + s)*16 + f] = o;
    }
    {
        const int base = (((2*Bb*Hh) + bh)*Ss + s)*16 + f;
        float4 c = qkv4[base], l = qkv4[base+dl], r = qkv4[base+dr];
        float4 o;
        o.x = w0*c.x + w1*(l.x + r.x);
        o.y = w0*c.y + w1*(l.y + r.y);
        o.z = w0*c.z + w1*(l.z + r.z);
        o.w = w0*c.w + w1*(l.w + r.w);
        ((float4*)g_vs)[(bh*Ss + s)*16 + f] = o;
    }
}

// ---------------------------------------------------------------------------
// Routed attention: one warp per query (b,h,s).
// ---------------------------------------------------------------------------
__global__ __launch_bounds__(256) void attn_kernel(const int* __restrict__ routes)
{
    __shared__ float qs    [8][64];
    __shared__ float attn_s[8][64];
    __shared__ int   rt_s  [8][64];

    const int warp = threadIdx.x >> 5;
    const int lane = threadIdx.x & 31;
    const int gq = blockIdx.x*8 + warp;      // (b*H + h)*S + s
    const int s  = gq & (Ss-1);
    const int bh = gq >> 9;

    const float* qrow = g_qkv + ((size_t)bh*Ss + s)*HDh;   // t=0
    const float* kb   = g_ks + (size_t)bh*Ss*HDh;
    const float* vb   = g_vs + (size_t)bh*Ss*HDh;

    if (lane < 16)
        ((float4*)qs[warp])[lane] = ((const float4*)qrow)[lane];
    const int r0 = routes[s*KR + lane];
    const int r1 = routes[s*KR + 32 + lane];
    rt_s[warp][lane]      = r0;
    rt_s[warp][lane + 32] = r1;
    __syncwarp();

    const float4* k0 = (const float4*)(kb + r0*HDh);
    const float4* k1 = (const float4*)(kb + r1*HDh);
    const float4* q4 = (const float4*)qs[warp];
    float a0 = 0.f, a1 = 0.f;
    #pragma unroll
    for (int d = 0; d < 16; ++d) {
        float4 qv = q4[d];
        float4 x0 = k0[d];
        float4 x1 = k1[d];
        a0 += qv.x*x0.x + qv.y*x0.y + qv.z*x0.z + qv.w*x0.w;
        a1 += qv.x*x1.x + qv.y*x1.y + qv.z*x1.z + qv.w*x1.w;
    }
    float sc0 = (r0 > s) ? -1e9f : a0 * kSCALE;
    float sc1 = (r1 > s) ? -1e9f : a1 * kSCALE;

    float mx = fmaxf(sc0, sc1);
    #pragma unroll
    for (int o = 16; o > 0; o >>= 1)
        mx = fmaxf(mx, __shfl_xor_sync(0xffffffffu, mx, o));
    float e0 = __expf(sc0 - mx);
    float e1 = __expf(sc1 - mx);
    float sum = e0 + e1;
    #pragma unroll
    for (int o = 16; o > 0; o >>= 1)
        sum += __shfl_xor_sync(0xffffffffu, sum, o);
    const float inv = 1.0f / sum;
    attn_s[warp][lane]      = e0 * inv;
    attn_s[warp][lane + 32] = e1 * inv;
    __syncwarp();

    float o0 = 0.f, o1 = 0.f;
    #pragma unroll 8
    for (int j = 0; j < KR; ++j) {
        const int   rj = rt_s[warp][j];
        const float w  = attn_s[warp][j];
        const float2 vv = *(const float2*)(vb + rj*HDh + 2*lane);
        o0 += w*vv.x;
        o1 += w*vv.y;
    }

    const int b = bh >> 4;
    const int h = bh & 15;
    float2* op = (float2*)(g_attnout + ((size_t)(b*Ss + s))*Dd + h*HDh) + lane;
    *op = make_float2(o0, o1);
}

// ---------------------------------------------------------------------------
extern "C" void kernel_launch(void* const* d_in, const int* in_sizes, int n_in,
                              void* d_out, int out_size)
{
    const float* x      = (const float*)d_in[0];   // [B,S,D]
    const float* w_qkv  = (const float*)d_in[1];   // [D, 3D]
    const float* b_qkv  = (const float*)d_in[2];   // [3D]
    const float* w_out  = (const float*)d_in[3];   // [D, D]
    const float* b_out  = (const float*)d_in[4];   // [D]
    const int*   routes = (const int*)d_in[5];     // [S, K]
    float* out = (float*)d_out;                    // [B,S,D]

    // 1) QKV projection + scatter into [t][bh][s][hd]
    {
        dim3 grid(THREE_D/128, Mrows/128);         // (24, 16)
        sgemm2_k<true, false><<<grid, 256>>>(Mrows, THREE_D, Dd, x, w_qkv, b_qkv, nullptr);
    }
    // 2) neighbor smoothing of K/V
    {
        const int total = Bb*Hh*Ss*16;
        smooth_kernel<<<(total + 255)/256, 256>>>();
    }
    // 3) routed attention -> g_attnout [B*S, D]
    {
        attn_kernel<<<(Bb*Hh*Ss)/8, 256>>>(routes);
    }
    // 4) output projection
    {
        dim3 grid(Dd/128, Mrows/128);              // (8, 16)
        sgemm2_k<false, true><<<grid, 256>>>(Mrows, Dd, Dd, nullptr, w_out, b_out, out);
    }
}